// round 4
// baseline (speedup 1.0000x reference)
#include <cuda_runtime.h>
#include <cuda_bf16.h>
#include <cstddef>

#define NN 50000
#define EE 850000

// ---------------- scratch (__device__ globals; alloc-free rule) ----------------
__device__ float g_featcat[NN * 384]; // layer fc outputs; layer3: [feat(192) | res3(192)]
__device__ float g_h1[NN * 128];
__device__ float g_h2[NN * 128];
__device__ float g_wcat[128 * 384];   // [W3 | resW3]
__device__ float g_el[NN * 6];
__device__ float g_er[NN * 6];
__device__ int   g_counts[NN];
__device__ int   g_cursor[NN];
__device__ int   g_rowstart[NN + 1];
__device__ int   g_csrc[EE];

// ---------------- CSR build ----------------
__global__ void k_zero(int n) {
    int i = blockIdx.x * blockDim.x + threadIdx.x;
    if (i < n) g_counts[i] = 0;
}
__global__ void k_hist(const int* __restrict__ dst, int E) {
    int e = blockIdx.x * blockDim.x + threadIdx.x;
    if (e < E) atomicAdd(&g_counts[dst[e]], 1);
}
__global__ void k_scan(int n) {
    __shared__ int sm[1024];
    __shared__ int s_off;
    int tid = threadIdx.x;
    if (tid == 0) s_off = 0;
    __syncthreads();
    for (int base = 0; base < n; base += 1024) {
        int i = base + tid;
        int v = (i < n) ? g_counts[i] : 0;
        sm[tid] = v;
        __syncthreads();
        #pragma unroll
        for (int d = 1; d < 1024; d <<= 1) {
            int t = (tid >= d) ? sm[tid - d] : 0;
            __syncthreads();
            sm[tid] += t;
            __syncthreads();
        }
        int off = s_off;
        if (i < n) {
            int ex = off + sm[tid] - v;
            g_rowstart[i] = ex;
            g_cursor[i]   = ex;
        }
        __syncthreads();
        if (tid == 1023) s_off = off + sm[1023];
        __syncthreads();
    }
    if (tid == 0) g_rowstart[n] = s_off;
}
__global__ void k_scatter(const int* __restrict__ src, const int* __restrict__ dst, int E) {
    int e = blockIdx.x * blockDim.x + threadIdx.x;
    if (e < E) {
        int p = atomicAdd(&g_cursor[dst[e]], 1);
        g_csrc[p] = src[e];
    }
}

// ---------------- W3|resW3 concat ----------------
__global__ void k_wcat(const float* __restrict__ W3, const float* __restrict__ rW3) {
    int idx = blockIdx.x * blockDim.x + threadIdx.x;
    if (idx < 128 * 192) {
        int r = idx / 192, c = idx % 192;
        g_wcat[r * 384 + c]       = W3[idx];
        g_wcat[r * 384 + 192 + c] = rW3[idx];
    }
}

// ---------------- double-buffered SGEMM, K=128, BM=BN=128, BK=16 ----------------
// FH>0: fused el/er epilogue (requires N==128, gridDim.x==1, heads FH)
template <int FH>
__global__ __launch_bounds__(256) void sgemm_db(
    const float* __restrict__ A, const float* __restrict__ B,
    float* __restrict__ C, int M, int N,
    const float* __restrict__ al, const float* __restrict__ ar)
{
    constexpr int BM = 128, BK = 16;
    __shared__ float As[2][BK][BM + 4];
    __shared__ float Bs[2][BK][128];
    const int tid  = threadIdx.x;
    const int brow = blockIdx.y * BM;
    const int bcol = blockIdx.x * 128;
    const int tr = (tid >> 4) * 8;
    const int tc = (tid & 15) * 8;

    const int amRow = tid >> 2;        // 0..63 (and +64)
    const int aK    = (tid & 3) << 2;  // 0,4,8,12
    const int bK    = tid >> 5;        // 0..7 (and +8)
    const int bN    = (tid & 31) << 2; // 0..124

    float acc[8][8];
    #pragma unroll
    for (int i = 0; i < 8; i++)
        #pragma unroll
        for (int j = 0; j < 8; j++) acc[i][j] = 0.f;

    float4 av[2], bv[2];
    #pragma unroll
    for (int t = 0; t < 2; t++) {
        int gm = brow + amRow + t * 64;
        av[t] = (gm < M) ? *reinterpret_cast<const float4*>(A + (size_t)gm * 128 + aK)
                         : make_float4(0.f, 0.f, 0.f, 0.f);
        bv[t] = *reinterpret_cast<const float4*>(B + (size_t)(bK + t * 8) * N + bcol + bN);
    }
    #pragma unroll
    for (int t = 0; t < 2; t++) {
        int m = amRow + t * 64;
        As[0][aK + 0][m] = av[t].x; As[0][aK + 1][m] = av[t].y;
        As[0][aK + 2][m] = av[t].z; As[0][aK + 3][m] = av[t].w;
        *reinterpret_cast<float4*>(&Bs[0][bK + t * 8][bN]) = bv[t];
    }
    __syncthreads();

    #pragma unroll
    for (int tile = 0; tile < 8; tile++) {
        const int s = tile & 1;
        if (tile < 7) {
            const int k0 = (tile + 1) * BK;
            #pragma unroll
            for (int t = 0; t < 2; t++) {
                int gm = brow + amRow + t * 64;
                av[t] = (gm < M) ? *reinterpret_cast<const float4*>(A + (size_t)gm * 128 + k0 + aK)
                                 : make_float4(0.f, 0.f, 0.f, 0.f);
                bv[t] = *reinterpret_cast<const float4*>(B + (size_t)(k0 + bK + t * 8) * N + bcol + bN);
            }
        }
        #pragma unroll
        for (int kk = 0; kk < BK; kk++) {
            float ra[8], rb[8];
            *reinterpret_cast<float4*>(&ra[0]) = *reinterpret_cast<const float4*>(&As[s][kk][tr]);
            *reinterpret_cast<float4*>(&ra[4]) = *reinterpret_cast<const float4*>(&As[s][kk][tr + 4]);
            *reinterpret_cast<float4*>(&rb[0]) = *reinterpret_cast<const float4*>(&Bs[s][kk][tc]);
            *reinterpret_cast<float4*>(&rb[4]) = *reinterpret_cast<const float4*>(&Bs[s][kk][tc + 4]);
            #pragma unroll
            for (int i = 0; i < 8; i++)
                #pragma unroll
                for (int j = 0; j < 8; j++)
                    acc[i][j] = fmaf(ra[i], rb[j], acc[i][j]);
        }
        if (tile < 7) {
            const int s2 = s ^ 1;
            #pragma unroll
            for (int t = 0; t < 2; t++) {
                int m = amRow + t * 64;
                As[s2][aK + 0][m] = av[t].x; As[s2][aK + 1][m] = av[t].y;
                As[s2][aK + 2][m] = av[t].z; As[s2][aK + 3][m] = av[t].w;
                *reinterpret_cast<float4*>(&Bs[s2][bK + t * 8][bN]) = bv[t];
            }
            __syncthreads();
        }
    }

    // store C
    #pragma unroll
    for (int i = 0; i < 8; i++) {
        int gm = brow + tr + i;
        if (gm < M) {
            #pragma unroll
            for (int j = 0; j < 8; j += 4) {
                int gn = bcol + tc + j;
                *reinterpret_cast<float4*>(C + (size_t)gm * N + gn) =
                    make_float4(acc[i][j], acc[i][j + 1], acc[i][j + 2], acc[i][j + 3]);
            }
        }
    }

    // fused el/er (layers 1,2): full feature row lives in this block.
    if (FH > 0) {
        const int head = (tid & 15) >> 2;          // tc/32
        #pragma unroll
        for (int i = 0; i < 8; i++) {
            float pl = 0.f, pr = 0.f;
            #pragma unroll
            for (int j = 0; j < 8; j++) {
                pl = fmaf(acc[i][j], al[tc + j], pl);
                pr = fmaf(acc[i][j], ar[tc + j], pr);
            }
            // reduce over the 4 threads sharing (row, head): tid bits 0..1
            pl += __shfl_xor_sync(0xffffffffu, pl, 1);
            pl += __shfl_xor_sync(0xffffffffu, pl, 2);
            pr += __shfl_xor_sync(0xffffffffu, pr, 1);
            pr += __shfl_xor_sync(0xffffffffu, pr, 2);
            int gm = brow + tr + i;
            if ((tid & 3) == 0 && gm < M) {
                g_el[gm * FH + head] = pl;
                g_er[gm * FH + head] = pr;
            }
        }
    }
}

// ---------------- el/er for layer 3 (strided feat) ----------------
template <int H>
__global__ void elr_kernel(const float* __restrict__ feat, int fstr,
                           const float* __restrict__ al, const float* __restrict__ ar, int n)
{
    int warp = (blockIdx.x * blockDim.x + threadIdx.x) >> 5;
    int lane = threadIdx.x & 31;
    if (warp >= n) return;
    const float* f = feat + (size_t)warp * fstr;
    #pragma unroll
    for (int h = 0; h < H; h++) {
        float v  = f[h * 32 + lane];
        float pl = v * al[h * 32 + lane];
        float pr = v * ar[h * 32 + lane];
        #pragma unroll
        for (int o = 16; o > 0; o >>= 1) {
            pl += __shfl_xor_sync(0xffffffffu, pl, o);
            pr += __shfl_xor_sync(0xffffffffu, pr, o);
        }
        if (lane == 0) {
            g_el[warp * H + h] = pl;
            g_er[warp * H + h] = pr;
        }
    }
}

// ---------------- aggregation: one warp per dst node, 2-edge unroll ----------------
template <int H, bool RELU, bool MEAN>
__global__ __launch_bounds__(256) void agg_kernel(
    const float* __restrict__ feat, int fstr,
    const float* __restrict__ bias,
    const float* __restrict__ residual, int rstr,
    float* __restrict__ out, int n)
{
    int warp = (blockIdx.x * blockDim.x + threadIdx.x) >> 5;
    int lane = threadIdx.x & 31;
    if (warp >= n) return;
    const int i = warp;

    float er_h = (lane < H) ? g_er[i * H + lane] : 0.f;

    float acc[H], denom[H];
    #pragma unroll
    for (int h = 0; h < H; h++) { acc[h] = 0.f; denom[h] = 0.f; }

    int p0 = g_rowstart[i], p1 = g_rowstart[i + 1];
    int p = p0;
    for (; p + 2 <= p1; p += 2) {
        int s0 = g_csrc[p], s1 = g_csrc[p + 1];
        float w0 = 0.f, w1 = 0.f;
        if (lane < H) {
            float e0 = g_el[s0 * H + lane] + er_h;
            e0 = (e0 > 0.f) ? e0 : 0.2f * e0;
            w0 = __expf(e0);
            float e1 = g_el[s1 * H + lane] + er_h;
            e1 = (e1 > 0.f) ? e1 : 0.2f * e1;
            w1 = __expf(e1);
        }
        const float* f0 = feat + (size_t)s0 * fstr;
        const float* f1 = feat + (size_t)s1 * fstr;
        float v0[H], v1[H];
        #pragma unroll
        for (int h = 0; h < H; h++) { v0[h] = f0[h * 32 + lane]; v1[h] = f1[h * 32 + lane]; }
        #pragma unroll
        for (int h = 0; h < H; h++) {
            float a0 = __shfl_sync(0xffffffffu, w0, h);
            float a1 = __shfl_sync(0xffffffffu, w1, h);
            denom[h] += a0 + a1;
            acc[h] = fmaf(a0, v0[h], acc[h]);
            acc[h] = fmaf(a1, v1[h], acc[h]);
        }
    }
    if (p < p1) {
        int s0 = g_csrc[p];
        float w0 = 0.f;
        if (lane < H) {
            float e0 = g_el[s0 * H + lane] + er_h;
            e0 = (e0 > 0.f) ? e0 : 0.2f * e0;
            w0 = __expf(e0);
        }
        const float* f0 = feat + (size_t)s0 * fstr;
        #pragma unroll
        for (int h = 0; h < H; h++) {
            float a0 = __shfl_sync(0xffffffffu, w0, h);
            denom[h] += a0;
            acc[h] = fmaf(a0, f0[h * 32 + lane], acc[h]);
        }
    }

    float msum = 0.f;
    #pragma unroll
    for (int h = 0; h < H; h++) {
        float r = acc[h] / fmaxf(denom[h], 1e-9f);
        if (residual) r += residual[(size_t)i * rstr + h * 32 + lane];
        r += bias[h * 32 + lane];
        if (RELU) r = fmaxf(r, 0.f);
        if (MEAN) msum += r;
        else      out[(size_t)i * fstr + h * 32 + lane] = r;
    }
    if (MEAN) out[i * 32 + lane] = msum * (1.f / H);
}

// ---------------- launch ----------------
extern "C" void kernel_launch(void* const* d_in, const int* in_sizes, int n_in,
                              void* d_out, int out_size)
{
    const float* x     = (const float*)d_in[0];
    const int*   src   = (const int*)  d_in[1];
    const int*   dst   = (const int*)  d_in[2];
    const float* W1    = (const float*)d_in[3];
    const float* al1   = (const float*)d_in[4];
    const float* ar1   = (const float*)d_in[5];
    const float* b1    = (const float*)d_in[6];
    const float* W2    = (const float*)d_in[7];
    const float* al2   = (const float*)d_in[8];
    const float* ar2   = (const float*)d_in[9];
    const float* b2    = (const float*)d_in[10];
    const float* W3    = (const float*)d_in[11];
    const float* al3   = (const float*)d_in[12];
    const float* ar3   = (const float*)d_in[13];
    const float* b3    = (const float*)d_in[14];
    const float* resW3 = (const float*)d_in[15];

    const int n = in_sizes[0] / 128;
    const int E = in_sizes[1];
    float* out = (float*)d_out;

    float *featcat, *h1, *h2, *wcat;
    cudaGetSymbolAddress((void**)&featcat, g_featcat);
    cudaGetSymbolAddress((void**)&h1,      g_h1);
    cudaGetSymbolAddress((void**)&h2,      g_h2);
    cudaGetSymbolAddress((void**)&wcat,    g_wcat);

    // ---- CSR build (by dst) + weight concat ----
    k_zero<<<(n + 255) / 256, 256>>>(n);
    k_hist<<<(E + 255) / 256, 256>>>(dst, E);
    k_scan<<<1, 1024>>>(n);
    k_scatter<<<(E + 255) / 256, 256>>>(src, dst, E);
    k_wcat<<<(128 * 192 + 255) / 256, 256>>>(W3, resW3);

    const dim3 grid1(1, (n + 127) / 128);
    const dim3 grid3(3, (n + 127) / 128);
    const int  wblocks = (n + 7) / 8;

    // ---- layer 1 (el/er fused into GEMM epilogue) ----
    sgemm_db<4><<<grid1, 256>>>(x, W1, featcat, n, 128, al1, ar1);
    agg_kernel<4, true, false><<<wblocks, 256>>>(featcat, 128, b1, nullptr, 0, h1, n);
    // ---- layer 2 (identity residual = h1) ----
    sgemm_db<4><<<grid1, 256>>>(h1, W2, featcat, n, 128, al2, ar2);
    agg_kernel<4, true, false><<<wblocks, 256>>>(featcat, 128, b2, h1, 128, h2, n);
    // ---- layer 3: one N=384 GEMM producing [feat | res3] ----
    sgemm_db<0><<<grid3, 256>>>(h2, wcat, featcat, n, 384, nullptr, nullptr);
    elr_kernel<6><<<wblocks, 256>>>(featcat, 384, al3, ar3, n);
    agg_kernel<6, false, true><<<wblocks, 256>>>(featcat, 384, b3, featcat + 192, 384, out, n);
}

// round 8
// speedup vs baseline: 1.4056x; 1.4056x over previous
#include <cuda_runtime.h>
#include <cuda_bf16.h>
#include <cstddef>

#define NN 50000
#define EE 850000

// ---------------- scratch (__device__ globals; alloc-free rule) ----------------
__device__ float g_featcat[NN * 384]; // layer fc outputs; layer3: [feat(192) | res3(192)]
__device__ float g_h1[NN * 128];
__device__ float g_h2[NN * 128];
__device__ float g_wcat[128 * 384];   // [W3 | resW3]
__device__ float g_el[NN * 6];
__device__ float g_er[NN * 6];
__device__ int   g_counts[NN];
__device__ int   g_cursor[NN];
__device__ int   g_rowstart[NN + 1];
__device__ int   g_csrc[EE];

// ---------------- CSR build ----------------
__global__ void k_zero(int n) {
    int i = blockIdx.x * blockDim.x + threadIdx.x;
    if (i < n) g_counts[i] = 0;
}
__global__ void k_hist(const int* __restrict__ dst, int E) {
    int e = blockIdx.x * blockDim.x + threadIdx.x;
    if (e < E) atomicAdd(&g_counts[dst[e]], 1);
}
__global__ void k_scan(int n) {
    __shared__ int sm[1024];
    __shared__ int s_off;
    int tid = threadIdx.x;
    if (tid == 0) s_off = 0;
    __syncthreads();
    for (int base = 0; base < n; base += 1024) {
        int i = base + tid;
        int v = (i < n) ? g_counts[i] : 0;
        sm[tid] = v;
        __syncthreads();
        #pragma unroll
        for (int d = 1; d < 1024; d <<= 1) {
            int t = (tid >= d) ? sm[tid - d] : 0;
            __syncthreads();
            sm[tid] += t;
            __syncthreads();
        }
        int off = s_off;
        if (i < n) {
            int ex = off + sm[tid] - v;
            g_rowstart[i] = ex;
            g_cursor[i]   = ex;
        }
        __syncthreads();
        if (tid == 1023) s_off = off + sm[1023];
        __syncthreads();
    }
    if (tid == 0) g_rowstart[n] = s_off;
}
__global__ void k_scatter(const int* __restrict__ src, const int* __restrict__ dst, int E) {
    int e = blockIdx.x * blockDim.x + threadIdx.x;
    if (e < E) {
        int p = atomicAdd(&g_cursor[dst[e]], 1);
        g_csrc[p] = src[e];
    }
}

// ---------------- W3|resW3 concat ----------------
__global__ void k_wcat(const float* __restrict__ W3, const float* __restrict__ rW3) {
    int idx = blockIdx.x * blockDim.x + threadIdx.x;
    if (idx < 128 * 192) {
        int r = idx / 192, c = idx % 192;
        g_wcat[r * 384 + c]       = W3[idx];
        g_wcat[r * 384 + 192 + c] = rW3[idx];
    }
}

// ---------------- double-buffered SGEMM, K=128, BM=128, BN=128, BK=16 ----------------
// Runtime tile loop (small I$ footprint). FH>0: fused el/er epilogue; columns
// >= FH*32 get zero coefficients so warp shuffles stay uniform.
template <int FH>
__global__ __launch_bounds__(256) void sgemm_db(
    const float* __restrict__ A, const float* __restrict__ B,
    float* __restrict__ C, int M, int N,
    const float* __restrict__ al, const float* __restrict__ ar)
{
    constexpr int BM = 128, BK = 16;
    __shared__ float As[2][BK][BM + 4];
    __shared__ float Bs[2][BK][128];
    const int tid  = threadIdx.x;
    const int brow = blockIdx.y * BM;
    const int bcol = blockIdx.x * 128;
    const int tr = (tid >> 4) * 8;
    const int tc = (tid & 15) * 8;

    const int amRow = tid >> 2;        // 0..63 (+64)
    const int aK    = (tid & 3) << 2;  // 0,4,8,12
    const int bK    = tid >> 5;        // 0..7 (+8)
    const int bN    = (tid & 31) << 2; // 0..124

    float acc[8][8];
    #pragma unroll
    for (int i = 0; i < 8; i++)
        #pragma unroll
        for (int j = 0; j < 8; j++) acc[i][j] = 0.f;

    float4 av[2], bv[2];
    // tile 0 load
    #pragma unroll
    for (int t = 0; t < 2; t++) {
        int gm = brow + amRow + t * 64;
        av[t] = (gm < M) ? *reinterpret_cast<const float4*>(A + (size_t)gm * 128 + aK)
                         : make_float4(0.f, 0.f, 0.f, 0.f);
        bv[t] = *reinterpret_cast<const float4*>(B + (size_t)(bK + t * 8) * N + bcol + bN);
    }
    #pragma unroll
    for (int t = 0; t < 2; t++) {
        int m = amRow + t * 64;
        As[0][aK + 0][m] = av[t].x; As[0][aK + 1][m] = av[t].y;
        As[0][aK + 2][m] = av[t].z; As[0][aK + 3][m] = av[t].w;
        *reinterpret_cast<float4*>(&Bs[0][bK + t * 8][bN]) = bv[t];
    }
    __syncthreads();

    int s = 0;
    #pragma unroll 1
    for (int tile = 0; tile < 8; tile++) {
        if (tile < 7) {
            const int k0 = (tile + 1) * BK;
            #pragma unroll
            for (int t = 0; t < 2; t++) {
                int gm = brow + amRow + t * 64;
                av[t] = (gm < M) ? *reinterpret_cast<const float4*>(A + (size_t)gm * 128 + k0 + aK)
                                 : make_float4(0.f, 0.f, 0.f, 0.f);
                bv[t] = *reinterpret_cast<const float4*>(B + (size_t)(k0 + bK + t * 8) * N + bcol + bN);
            }
        }
        #pragma unroll
        for (int kk = 0; kk < BK; kk++) {
            float ra[8], rb[8];
            *reinterpret_cast<float4*>(&ra[0]) = *reinterpret_cast<const float4*>(&As[s][kk][tr]);
            *reinterpret_cast<float4*>(&ra[4]) = *reinterpret_cast<const float4*>(&As[s][kk][tr + 4]);
            *reinterpret_cast<float4*>(&rb[0]) = *reinterpret_cast<const float4*>(&Bs[s][kk][tc]);
            *reinterpret_cast<float4*>(&rb[4]) = *reinterpret_cast<const float4*>(&Bs[s][kk][tc + 4]);
            #pragma unroll
            for (int i = 0; i < 8; i++)
                #pragma unroll
                for (int j = 0; j < 8; j++)
                    acc[i][j] = fmaf(ra[i], rb[j], acc[i][j]);
        }
        if (tile < 7) {
            const int s2 = s ^ 1;
            #pragma unroll
            for (int t = 0; t < 2; t++) {
                int m = amRow + t * 64;
                As[s2][aK + 0][m] = av[t].x; As[s2][aK + 1][m] = av[t].y;
                As[s2][aK + 2][m] = av[t].z; As[s2][aK + 3][m] = av[t].w;
                *reinterpret_cast<float4*>(&Bs[s2][bK + t * 8][bN]) = bv[t];
            }
            __syncthreads();
            s = s2;
        }
    }

    // store C
    #pragma unroll
    for (int i = 0; i < 8; i++) {
        int gm = brow + tr + i;
        if (gm < M) {
            #pragma unroll
            for (int j = 0; j < 8; j += 4) {
                int gn = bcol + tc + j;
                *reinterpret_cast<float4*>(C + (size_t)gm * N + gn) =
                    make_float4(acc[i][j], acc[i][j + 1], acc[i][j + 2], acc[i][j + 3]);
            }
        }
    }

    // fused el/er epilogue. Head columns are [0, FH*32); other columns get
    // zero coefficients so the 4-lane shuffle reductions stay warp-uniform.
    if (FH > 0) {
        const int gcol = bcol + tc;
        const int head = gcol >> 5;     // uniform across each 4-thread group
        float alv[8], arv[8];
        #pragma unroll
        for (int j = 0; j < 8; j++) {
            bool in = (gcol + j) < FH * 32;
            alv[j] = in ? al[gcol + j] : 0.f;
            arv[j] = in ? ar[gcol + j] : 0.f;
        }
        #pragma unroll
        for (int i = 0; i < 8; i++) {
            float pl = 0.f, pr = 0.f;
            #pragma unroll
            for (int j = 0; j < 8; j++) {
                pl = fmaf(acc[i][j], alv[j], pl);
                pr = fmaf(acc[i][j], arv[j], pr);
            }
            pl += __shfl_xor_sync(0xffffffffu, pl, 1);
            pl += __shfl_xor_sync(0xffffffffu, pl, 2);
            pr += __shfl_xor_sync(0xffffffffu, pr, 1);
            pr += __shfl_xor_sync(0xffffffffu, pr, 2);
            int gm = brow + tr + i;
            if ((tid & 3) == 0 && gm < M && head < FH) {
                g_el[gm * FH + head] = pl;
                g_er[gm * FH + head] = pr;
            }
        }
    }
}

// ---------------- aggregation: one warp per dst node, 2-edge unroll ----------------
template <int H, bool RELU, bool MEAN>
__global__ __launch_bounds__(256) void agg_kernel(
    const float* __restrict__ feat, int fstr,
    const float* __restrict__ bias,
    const float* __restrict__ residual, int rstr,
    float* __restrict__ out, int n)
{
    int warp = (blockIdx.x * blockDim.x + threadIdx.x) >> 5;
    int lane = threadIdx.x & 31;
    if (warp >= n) return;
    const int i = warp;

    float er_h = (lane < H) ? g_er[i * H + lane] : 0.f;

    float acc[H], denom[H];
    #pragma unroll
    for (int h = 0; h < H; h++) { acc[h] = 0.f; denom[h] = 0.f; }

    int p0 = g_rowstart[i], p1 = g_rowstart[i + 1];
    int p = p0;
    for (; p + 2 <= p1; p += 2) {
        int s0 = g_csrc[p], s1 = g_csrc[p + 1];
        float w0 = 0.f, w1 = 0.f;
        if (lane < H) {
            float e0 = g_el[s0 * H + lane] + er_h;
            e0 = (e0 > 0.f) ? e0 : 0.2f * e0;
            w0 = __expf(e0);
            float e1 = g_el[s1 * H + lane] + er_h;
            e1 = (e1 > 0.f) ? e1 : 0.2f * e1;
            w1 = __expf(e1);
        }
        const float* f0 = feat + (size_t)s0 * fstr;
        const float* f1 = feat + (size_t)s1 * fstr;
        float v0[H], v1[H];
        #pragma unroll
        for (int h = 0; h < H; h++) { v0[h] = f0[h * 32 + lane]; v1[h] = f1[h * 32 + lane]; }
        #pragma unroll
        for (int h = 0; h < H; h++) {
            float a0 = __shfl_sync(0xffffffffu, w0, h);
            float a1 = __shfl_sync(0xffffffffu, w1, h);
            denom[h] += a0 + a1;
            acc[h] = fmaf(a0, v0[h], acc[h]);
            acc[h] = fmaf(a1, v1[h], acc[h]);
        }
    }
    if (p < p1) {
        int s0 = g_csrc[p];
        float w0 = 0.f;
        if (lane < H) {
            float e0 = g_el[s0 * H + lane] + er_h;
            e0 = (e0 > 0.f) ? e0 : 0.2f * e0;
            w0 = __expf(e0);
        }
        const float* f0 = feat + (size_t)s0 * fstr;
        #pragma unroll
        for (int h = 0; h < H; h++) {
            float a0 = __shfl_sync(0xffffffffu, w0, h);
            denom[h] += a0;
            acc[h] = fmaf(a0, f0[h * 32 + lane], acc[h]);
        }
    }

    float msum = 0.f;
    #pragma unroll
    for (int h = 0; h < H; h++) {
        float r = acc[h] / fmaxf(denom[h], 1e-9f);
        if (residual) r += residual[(size_t)i * rstr + h * 32 + lane];
        r += bias[h * 32 + lane];
        if (RELU) r = fmaxf(r, 0.f);
        if (MEAN) msum += r;
        else      out[(size_t)i * fstr + h * 32 + lane] = r;
    }
    if (MEAN) out[i * 32 + lane] = msum * (1.f / H);
}

// ---------------- launch ----------------
extern "C" void kernel_launch(void* const* d_in, const int* in_sizes, int n_in,
                              void* d_out, int out_size)
{
    const float* x     = (const float*)d_in[0];
    const int*   src   = (const int*)  d_in[1];
    const int*   dst   = (const int*)  d_in[2];
    const float* W1    = (const float*)d_in[3];
    const float* al1   = (const float*)d_in[4];
    const float* ar1   = (const float*)d_in[5];
    const float* b1    = (const float*)d_in[6];
    const float* W2    = (const float*)d_in[7];
    const float* al2   = (const float*)d_in[8];
    const float* ar2   = (const float*)d_in[9];
    const float* b2    = (const float*)d_in[10];
    const float* W3    = (const float*)d_in[11];
    const float* al3   = (const float*)d_in[12];
    const float* ar3   = (const float*)d_in[13];
    const float* b3    = (const float*)d_in[14];
    const float* resW3 = (const float*)d_in[15];

    const int n = in_sizes[0] / 128;
    const int E = in_sizes[1];
    float* out = (float*)d_out;

    float *featcat, *h1, *h2, *wcat;
    cudaGetSymbolAddress((void**)&featcat, g_featcat);
    cudaGetSymbolAddress((void**)&h1,      g_h1);
    cudaGetSymbolAddress((void**)&h2,      g_h2);
    cudaGetSymbolAddress((void**)&wcat,    g_wcat);

    // ---- CSR build (by dst) + weight concat ----
    k_zero<<<(n + 255) / 256, 256>>>(n);
    k_hist<<<(E + 255) / 256, 256>>>(dst, E);
    k_scan<<<1, 1024>>>(n);
    k_scatter<<<(E + 255) / 256, 256>>>(src, dst, E);
    k_wcat<<<(128 * 192 + 255) / 256, 256>>>(W3, resW3);

    const dim3 grid1(1, (n + 127) / 128);
    const dim3 grid3(3, (n + 127) / 128);
    const int  wblocks = (n + 7) / 8;

    // ---- layer 1 (el/er fused into GEMM epilogue) ----
    sgemm_db<4><<<grid1, 256>>>(x, W1, featcat, n, 128, al1, ar1);
    agg_kernel<4, true, false><<<wblocks, 256>>>(featcat, 128, b1, nullptr, 0, h1, n);
    // ---- layer 2 (identity residual = h1) ----
    sgemm_db<4><<<grid1, 256>>>(h1, W2, featcat, n, 128, al2, ar2);
    agg_kernel<4, true, false><<<wblocks, 256>>>(featcat, 128, b2, h1, 128, h2, n);
    // ---- layer 3: one N=384 GEMM producing [feat | res3], el/er fused ----
    sgemm_db<6><<<grid3, 256>>>(h2, wcat, featcat, n, 384, al3, ar3);
    agg_kernel<6, false, true><<<wblocks, 256>>>(featcat, 384, b3, featcat + 192, 384, out, n);
}